// round 1
// baseline (speedup 1.0000x reference)
#include <cuda_runtime.h>
#include <math.h>

#define Bsz 128
#define D 100
#define D2 10000
#define M_ROWS 12800   // B*D

// Scratch (device globals; no allocation allowed)
__device__ float g_G0[M_ROWS];       // gelu(z)
__device__ float g_G1[M_ROWS];       // gelu'(z)
__device__ float g_G2[M_ROWS];       // gelu''(z)
__device__ float g_AJ[M_ROWS * D];   // W2[o,k]*g1[b,k]
__device__ float g_AH[M_ROWS * D];   // W2[o,k]*g2[b,k]
__device__ float g_P [D * D2];       // W1[k,i]*W1[k,j]

// ---------------- prep: z, gelu derivatives ----------------
__global__ void prep_kernel(const float* __restrict__ x,
                            const float* __restrict__ W1,
                            const float* __restrict__ b1) {
    int b = blockIdx.x;
    __shared__ float xs[D];
    int t = threadIdx.x;
    if (t < D) xs[t] = x[b * D + t];
    __syncthreads();
    if (t < D) {
        const float* w = W1 + t * D;
        float z = b1[t];
        #pragma unroll 4
        for (int i = 0; i < D; i++) z = fmaf(w[i], xs[i], z);
        float cdf = 0.5f * (1.0f + erff(z * 0.70710678118654752f));
        float pdf = 0.39894228040143268f * expf(-0.5f * z * z);
        g_G0[b * D + t] = z * cdf;
        g_G1[b * D + t] = cdf + z * pdf;
        g_G2[b * D + t] = (2.0f - z * z) * pdf;
    }
}

// ---------------- out = g0 @ W2^T + b2 ----------------
__global__ void out_kernel(const float* __restrict__ W2,
                           const float* __restrict__ b2,
                           float* __restrict__ out) {
    int b = blockIdx.x;
    __shared__ float gs[D];
    int t = threadIdx.x;
    if (t < D) gs[t] = g_G0[b * D + t];
    __syncthreads();
    if (t < D) {
        const float* w = W2 + t * D;
        float acc = b2[t];
        #pragma unroll 4
        for (int k = 0; k < D; k++) acc = fmaf(w[k], gs[k], acc);
        out[b * D + t] = acc;
    }
}

// ---------------- A matrices: row-scaled W2 ----------------
__global__ void buildA_kernel(const float* __restrict__ W2) {
    int m = blockIdx.x;          // m = b*100 + o
    int b = m / D, o = m % D;
    int k = threadIdx.x;
    if (k < D) {
        float w = W2[o * D + k];
        g_AJ[m * D + k] = w * g_G1[b * D + k];
        g_AH[m * D + k] = w * g_G2[b * D + k];
    }
}

// ---------------- P[k, i*100+j] = W1[k,i]*W1[k,j] ----------------
__global__ void buildP_kernel(const float* __restrict__ W1) {
    int k = blockIdx.x;
    __shared__ float w[D];
    if (threadIdx.x < D) w[threadIdx.x] = W1[k * D + threadIdx.x];
    __syncthreads();
    float* Prow = g_P + k * D2;
    for (int t = threadIdx.x; t < D2; t += blockDim.x) {
        Prow[t] = w[t / D] * w[t % D];
    }
}

// ---------------- generic 64x64 tiled fp32 GEMM ----------------
// C[M,N] = A[M,K] @ B[K,N].  which: 0 -> A=g_AJ, B=Bext ; 1 -> A=g_AH, B=g_P
#define BK 16
__global__ void gemm64_kernel(const float* __restrict__ Bext,
                              float* __restrict__ C,
                              int M, int N, int K, int which) {
    const float* __restrict__ A = which ? g_AH : g_AJ;
    const float* __restrict__ Bm = which ? (const float*)g_P : Bext;

    __shared__ float As[BK][68];   // padded pitch (68*4 bytes, 16B-aligned rows)
    __shared__ float Bs[BK][68];

    int tx = threadIdx.x & 15;     // 16
    int ty = threadIdx.x >> 4;     // 16
    int tid = threadIdx.x;

    int m0 = blockIdx.y * 64;
    int n0 = blockIdx.x * 64;

    float acc[4][4];
    #pragma unroll
    for (int r = 0; r < 4; r++)
        #pragma unroll
        for (int c = 0; c < 4; c++) acc[r][c] = 0.0f;

    for (int k0 = 0; k0 < K; k0 += BK) {
        // load A tile 64x16 -> As[k][m]
        {
            int col = tid & 15;            // k
            int rowb = (tid >> 4) * 4;     // m
            #pragma unroll
            for (int e = 0; e < 4; e++) {
                int row = rowb + e;
                float v = 0.0f;
                if (m0 + row < M && k0 + col < K)
                    v = A[(size_t)(m0 + row) * K + k0 + col];
                As[col][row] = v;
            }
        }
        // load B tile 16x64 -> Bs[k][n]
        {
            #pragma unroll
            for (int e = 0; e < 4; e++) {
                int idx = tid + e * 256;
                int row = idx >> 6;        // k
                int col = idx & 63;        // n
                float v = 0.0f;
                if (k0 + row < K && n0 + col < N)
                    v = Bm[(size_t)(k0 + row) * N + n0 + col];
                Bs[row][col] = v;
            }
        }
        __syncthreads();

        #pragma unroll
        for (int kk = 0; kk < BK; kk++) {
            float4 av = *reinterpret_cast<const float4*>(&As[kk][ty * 4]);
            float4 bv = *reinterpret_cast<const float4*>(&Bs[kk][tx * 4]);
            float ar[4] = {av.x, av.y, av.z, av.w};
            float br[4] = {bv.x, bv.y, bv.z, bv.w};
            #pragma unroll
            for (int r = 0; r < 4; r++)
                #pragma unroll
                for (int c = 0; c < 4; c++)
                    acc[r][c] = fmaf(ar[r], br[c], acc[r][c]);
        }
        __syncthreads();
    }

    // store
    int row0 = m0 + ty * 4;
    int col0 = n0 + tx * 4;
    #pragma unroll
    for (int r = 0; r < 4; r++) {
        int row = row0 + r;
        if (row >= M) continue;
        if (col0 + 3 < N) {
            float4 v = make_float4(acc[r][0], acc[r][1], acc[r][2], acc[r][3]);
            *reinterpret_cast<float4*>(&C[(size_t)row * N + col0]) = v;
        } else {
            #pragma unroll
            for (int c = 0; c < 4; c++)
                if (col0 + c < N) C[(size_t)row * N + col0 + c] = acc[r][c];
        }
    }
}

extern "C" void kernel_launch(void* const* d_in, const int* in_sizes, int n_in,
                              void* d_out, int out_size) {
    const float* x  = (const float*)d_in[0];
    const float* W1 = (const float*)d_in[1];
    const float* b1 = (const float*)d_in[2];
    const float* W2 = (const float*)d_in[3];
    const float* b2 = (const float*)d_in[4];

    float* out  = (float*)d_out;                       // 12800
    float* jac  = out + Bsz * D;                       // 1,280,000
    float* hess = jac + (size_t)Bsz * D * D;           // 128,000,000

    prep_kernel<<<Bsz, 128>>>(x, W1, b1);
    out_kernel<<<Bsz, 128>>>(W2, b2, out);
    buildA_kernel<<<M_ROWS, 128>>>(W2);
    buildP_kernel<<<D, 256>>>(W1);

    // jac = AJ(12800x100) @ W1(100x100)
    {
        dim3 grid((D + 63) / 64, M_ROWS / 64);
        gemm64_kernel<<<grid, 256>>>(W1, jac, M_ROWS, D, D, 0);
    }
    // hess = AH(12800x100) @ P(100x10000)
    {
        dim3 grid((D2 + 63) / 64, M_ROWS / 64);
        gemm64_kernel<<<grid, 256>>>(nullptr, hess, M_ROWS, D2, D, 1);
    }
}

// round 4
// speedup vs baseline: 3.9012x; 3.9012x over previous
#include <cuda_runtime.h>
#include <cuda_bf16.h>
#include <math.h>
#include <stdint.h>

#define Bsz 128
#define D 100
#define D2 10000
#define M_ROWS 12800      // B*D
#define KP 128            // padded K (storage)
#define K_STEPS 7         // 7*16 = 112 >= 100
#define N_PAD 10112       // 79 * 128
#define NJ_PAD 128

// ---------------- scratch (device globals) ----------------
__device__ float g_G0[M_ROWS];
__device__ float g_G1[M_ROWS];
__device__ float g_G2[M_ROWS];
__device__ __nv_bfloat16 g_AJh[M_ROWS * KP];
__device__ __nv_bfloat16 g_AJl[M_ROWS * KP];
__device__ __nv_bfloat16 g_AHh[M_ROWS * KP];
__device__ __nv_bfloat16 g_AHl[M_ROWS * KP];
__device__ __nv_bfloat16 g_PBh[(size_t)N_PAD * KP];   // Pt[n,k] = W1[k,i]*W1[k,j]
__device__ __nv_bfloat16 g_PBl[(size_t)N_PAD * KP];
__device__ __nv_bfloat16 g_BJh[NJ_PAD * KP];          // BJ[n=i,k] = W1[k,i]
__device__ __nv_bfloat16 g_BJl[NJ_PAD * KP];

// ---------------- helpers ----------------
__device__ __forceinline__ uint32_t smem_to_u32(const void* p) {
    uint32_t a;
    asm("{ .reg .u64 t; cvta.to.shared.u64 t, %1; cvt.u32.u64 %0, t; }" : "=r"(a) : "l"(p));
    return a;
}
__device__ __forceinline__ void split_bf16(float v, __nv_bfloat16& h, __nv_bfloat16& l) {
    h = __float2bfloat16_rn(v);
    l = __float2bfloat16_rn(v - __bfloat162float(h));
}
__device__ __forceinline__ void ldm4(uint32_t r[4], uint32_t addr) {
    asm volatile("ldmatrix.sync.aligned.m8n8.x4.shared.b16 {%0,%1,%2,%3}, [%4];"
                 : "=r"(r[0]), "=r"(r[1]), "=r"(r[2]), "=r"(r[3]) : "r"(addr));
}
__device__ __forceinline__ void mma_bf16(float c[4], const uint32_t a[4],
                                         uint32_t b0, uint32_t b1) {
    asm volatile(
        "mma.sync.aligned.m16n8k16.row.col.f32.bf16.bf16.f32 "
        "{%0,%1,%2,%3}, {%4,%5,%6,%7}, {%8,%9}, {%0,%1,%2,%3};"
        : "+f"(c[0]), "+f"(c[1]), "+f"(c[2]), "+f"(c[3])
        : "r"(a[0]), "r"(a[1]), "r"(a[2]), "r"(a[3]), "r"(b0), "r"(b1));
}

// ---------------- prep: z, gelu derivatives ----------------
__global__ void prep_kernel(const float* __restrict__ x,
                            const float* __restrict__ W1,
                            const float* __restrict__ b1) {
    int b = blockIdx.x;
    __shared__ float xs[D];
    int t = threadIdx.x;
    if (t < D) xs[t] = x[b * D + t];
    __syncthreads();
    if (t < D) {
        const float* w = W1 + t * D;
        float z = b1[t];
        #pragma unroll 4
        for (int i = 0; i < D; i++) z = fmaf(w[i], xs[i], z);
        float cdf = 0.5f * (1.0f + erff(z * 0.70710678118654752f));
        float pdf = 0.39894228040143268f * expf(-0.5f * z * z);
        g_G0[b * D + t] = z * cdf;
        g_G1[b * D + t] = cdf + z * pdf;
        g_G2[b * D + t] = (2.0f - z * z) * pdf;
    }
}

__global__ void out_kernel(const float* __restrict__ W2,
                           const float* __restrict__ b2,
                           float* __restrict__ out) {
    int b = blockIdx.x;
    __shared__ float gs[D];
    int t = threadIdx.x;
    if (t < D) gs[t] = g_G0[b * D + t];
    __syncthreads();
    if (t < D) {
        const float* w = W2 + t * D;
        float acc = b2[t];
        #pragma unroll 4
        for (int k = 0; k < D; k++) acc = fmaf(w[k], gs[k], acc);
        out[b * D + t] = acc;
    }
}

// ---------------- A matrices: row-scaled W2 -> bf16 split ----------------
__global__ void buildA_kernel(const float* __restrict__ W2) {
    int m = blockIdx.x;          // m = b*100 + o
    int b = m / D, o = m % D;
    int k = threadIdx.x;         // 128
    float aj = 0.0f, ah = 0.0f;
    if (k < D) {
        float w = W2[o * D + k];
        aj = w * g_G1[b * D + k];
        ah = w * g_G2[b * D + k];
    }
    __nv_bfloat16 h, l;
    split_bf16(aj, h, l);
    g_AJh[m * KP + k] = h; g_AJl[m * KP + k] = l;
    split_bf16(ah, h, l);
    g_AHh[m * KP + k] = h; g_AHl[m * KP + k] = l;
}

// ---------------- Pt[n,k] = W1[k,i]*W1[k,j], bf16 split ----------------
__global__ void buildP_kernel(const float* __restrict__ W1) {
    int n = blockIdx.x;   // N_PAD
    int k = threadIdx.x;  // 128
    float v = 0.0f;
    if (n < D2 && k < D) {
        int i = n / D, j = n % D;
        v = __ldg(W1 + k * D + i) * __ldg(W1 + k * D + j);
    }
    __nv_bfloat16 h, l;
    split_bf16(v, h, l);
    g_PBh[(size_t)n * KP + k] = h;
    g_PBl[(size_t)n * KP + k] = l;
}

// ---------------- BJ[n=i,k] = W1[k,i], bf16 split ----------------
__global__ void buildBJ_kernel(const float* __restrict__ W1) {
    int n = blockIdx.x;   // 128
    int k = threadIdx.x;  // 128
    float v = (n < D && k < D) ? W1[k * D + n] : 0.0f;
    __nv_bfloat16 h, l;
    split_bf16(v, h, l);
    g_BJh[n * KP + k] = h;
    g_BJl[n * KP + k] = l;
}

// ---------------- HMMA GEMM ----------------
// C tile(128x128) = Ah*Bh + Ah*Bl + Al*Bh  (A:[m,KP], B:[n,KP], both K-major)
// which: 0 -> A=g_AJ*, B=g_BJ* ; 1 -> A=g_AH*, B=g_PB*
#define PITCH 272                      // bytes per smem row (128 bf16 + 8 pad)
#define TILE_BYTES (128 * PITCH)       // 34816

template <int ROWS>
__device__ __forceinline__ void load_tile(char* dst, const __nv_bfloat16* __restrict__ src,
                                          int row0, int tid) {
    #pragma unroll
    for (int it = 0; it < ROWS * 16 / 256; it++) {
        int c = tid + it * 256;
        int row = c >> 4, col = c & 15;
        uint4 v = *reinterpret_cast<const uint4*>(src + (size_t)(row0 + row) * KP + col * 8);
        *reinterpret_cast<uint4*>(dst + row * PITCH + col * 16) = v;
    }
}

__global__ void __launch_bounds__(256, 1)
mma_gemm_kernel(float* __restrict__ C, int Nout, int which) {
    const __nv_bfloat16* __restrict__ Ah = which ? g_AHh : g_AJh;
    const __nv_bfloat16* __restrict__ Al = which ? g_AHl : g_AJl;
    const __nv_bfloat16* __restrict__ Bh = which ? g_PBh : g_BJh;
    const __nv_bfloat16* __restrict__ Bl = which ? g_PBl : g_BJl;

    extern __shared__ char smem[];
    char* sAh = smem;
    char* sAl = smem + TILE_BYTES;
    char* sBh = smem + 2 * TILE_BYTES;
    char* sBl = smem + 3 * TILE_BYTES;

    int tid = threadIdx.x;
    int m0 = blockIdx.y * 128;
    int n0 = blockIdx.x * 128;

    load_tile<128>(sAh, Ah, m0, tid);
    load_tile<128>(sAl, Al, m0, tid);
    load_tile<128>(sBh, Bh, n0, tid);
    load_tile<128>(sBl, Bl, n0, tid);
    __syncthreads();

    int lane = tid & 31, wid = tid >> 5;
    int wm = (wid & 1) * 64;      // warp m-offset
    int wn = (wid >> 1) * 32;     // warp n-offset
    int t = lane >> 3, r = lane & 7;

    // ldmatrix lane offsets (bytes)
    uint32_t aoff = (uint32_t)((wm + (t & 1) * 8 + r) * PITCH + (t >> 1) * 16);
    uint32_t boff = (uint32_t)((wn + (t >> 1) * 8 + r) * PITCH + (t & 1) * 16);

    uint32_t uAh = smem_to_u32(sAh), uAl = smem_to_u32(sAl);
    uint32_t uBh = smem_to_u32(sBh), uBl = smem_to_u32(sBl);

    float acc[4][4][4];
    #pragma unroll
    for (int i = 0; i < 4; i++)
        #pragma unroll
        for (int j = 0; j < 4; j++)
            #pragma unroll
            for (int e = 0; e < 4; e++) acc[i][j][e] = 0.0f;

    #pragma unroll
    for (int ks = 0; ks < K_STEPS; ks++) {
        uint32_t kb = ks * 32;
        uint32_t ah[4][4], al[4][4], bh[2][4], bl[2][4];
        #pragma unroll
        for (int mf = 0; mf < 4; mf++) ldm4(ah[mf], uAh + aoff + mf * 16 * PITCH + kb);
        #pragma unroll
        for (int bf = 0; bf < 2; bf++) ldm4(bh[bf], uBh + boff + bf * 16 * PITCH + kb);
        #pragma unroll
        for (int mf = 0; mf < 4; mf++)
            #pragma unroll
            for (int nf = 0; nf < 4; nf++)
                mma_bf16(acc[mf][nf], ah[mf], bh[nf >> 1][(nf & 1) * 2], bh[nf >> 1][(nf & 1) * 2 + 1]);

        #pragma unroll
        for (int bf = 0; bf < 2; bf++) ldm4(bl[bf], uBl + boff + bf * 16 * PITCH + kb);
        #pragma unroll
        for (int mf = 0; mf < 4; mf++)
            #pragma unroll
            for (int nf = 0; nf < 4; nf++)
                mma_bf16(acc[mf][nf], ah[mf], bl[nf >> 1][(nf & 1) * 2], bl[nf >> 1][(nf & 1) * 2 + 1]);

        #pragma unroll
        for (int mf = 0; mf < 4; mf++) ldm4(al[mf], uAl + aoff + mf * 16 * PITCH + kb);
        #pragma unroll
        for (int mf = 0; mf < 4; mf++)
            #pragma unroll
            for (int nf = 0; nf < 4; nf++)
                mma_bf16(acc[mf][nf], al[mf], bh[nf >> 1][(nf & 1) * 2], bh[nf >> 1][(nf & 1) * 2 + 1]);
    }

    // epilogue: direct register -> gmem stores (float2, 8B aligned; Nout is even)
    #pragma unroll
    for (int mf = 0; mf < 4; mf++) {
        int m = m0 + wm + mf * 16 + (lane >> 2);
        #pragma unroll
        for (int nf = 0; nf < 4; nf++) {
            int n = n0 + wn + nf * 8 + 2 * (lane & 3);
            if (n < Nout) {
                float2 v0 = make_float2(acc[mf][nf][0], acc[mf][nf][1]);
                float2 v1 = make_float2(acc[mf][nf][2], acc[mf][nf][3]);
                *reinterpret_cast<float2*>(&C[(size_t)m * Nout + n]) = v0;
                *reinterpret_cast<float2*>(&C[(size_t)(m + 8) * Nout + n]) = v1;
            }
        }
    }
}

// ---------------- host ----------------
extern "C" void kernel_launch(void* const* d_in, const int* in_sizes, int n_in,
                              void* d_out, int out_size) {
    const float* x  = (const float*)d_in[0];
    const float* W1 = (const float*)d_in[1];
    const float* b1 = (const float*)d_in[2];
    const float* W2 = (const float*)d_in[3];
    const float* b2 = (const float*)d_in[4];

    float* out  = (float*)d_out;
    float* jac  = out + Bsz * D;
    float* hess = jac + (size_t)Bsz * D * D;

    constexpr int SMEM_BYTES = 4 * TILE_BYTES;  // 139264
    cudaFuncSetAttribute(mma_gemm_kernel, cudaFuncAttributeMaxDynamicSharedMemorySize, SMEM_BYTES);

    prep_kernel<<<Bsz, 128>>>(x, W1, b1);
    out_kernel<<<Bsz, 128>>>(W2, b2, out);
    buildA_kernel<<<M_ROWS, 128>>>(W2);
    buildP_kernel<<<N_PAD, 128>>>(W1);
    buildBJ_kernel<<<NJ_PAD, 128>>>(W1);

    // jac = AJ(12800x100) @ W1^T-layout  (1 n-tile)
    {
        dim3 grid(1, M_ROWS / 128);
        mma_gemm_kernel<<<grid, 256, SMEM_BYTES>>>(jac, D, 0);
    }
    // hess = AH(12800x100) @ P(100x10000)  (79 n-tiles)
    {
        dim3 grid(N_PAD / 128, M_ROWS / 128);
        mma_gemm_kernel<<<grid, 256, SMEM_BYTES>>>(hess, D2, 1);
    }
}

// round 5
// speedup vs baseline: 3.9602x; 1.0151x over previous
#include <cuda_runtime.h>
#include <cuda_bf16.h>
#include <math.h>
#include <stdint.h>

#define Bsz 128
#define D 100
#define D2 10000
#define M_ROWS 12800      // B*D
#define KP 128            // padded K (storage in gmem scratch)
#define K_STEPS 7         // 7*16 = 112 >= 100
#define NTILE 96
#define N_PAD 10080       // 105 * 96
#define NJ_PAD 192        // 2 * 96

// ---------------- scratch (device globals) ----------------
__device__ float g_G0[M_ROWS];
__device__ float g_G1[M_ROWS];
__device__ float g_G2[M_ROWS];
__device__ __nv_bfloat16 g_AJh[M_ROWS * KP];
__device__ __nv_bfloat16 g_AJl[M_ROWS * KP];
__device__ __nv_bfloat16 g_AHh[M_ROWS * KP];
__device__ __nv_bfloat16 g_AHl[M_ROWS * KP];
__device__ __nv_bfloat16 g_PBh[(size_t)N_PAD * KP];   // Pt[n,k] = W1[k,i]*W1[k,j]
__device__ __nv_bfloat16 g_PBl[(size_t)N_PAD * KP];
__device__ __nv_bfloat16 g_BJh[NJ_PAD * KP];          // BJ[n=i,k] = W1[k,i]
__device__ __nv_bfloat16 g_BJl[NJ_PAD * KP];

// ---------------- helpers ----------------
__device__ __forceinline__ uint32_t smem_to_u32(const void* p) {
    uint32_t a;
    asm("{ .reg .u64 t; cvta.to.shared.u64 t, %1; cvt.u32.u64 %0, t; }" : "=r"(a) : "l"(p));
    return a;
}
__device__ __forceinline__ void split_bf16(float v, __nv_bfloat16& h, __nv_bfloat16& l) {
    h = __float2bfloat16_rn(v);
    l = __float2bfloat16_rn(v - __bfloat162float(h));
}
__device__ __forceinline__ void ldm4(uint32_t r[4], uint32_t addr) {
    asm volatile("ldmatrix.sync.aligned.m8n8.x4.shared.b16 {%0,%1,%2,%3}, [%4];"
                 : "=r"(r[0]), "=r"(r[1]), "=r"(r[2]), "=r"(r[3]) : "r"(addr));
}
__device__ __forceinline__ void ldm2(uint32_t r[2], uint32_t addr) {
    asm volatile("ldmatrix.sync.aligned.m8n8.x2.shared.b16 {%0,%1}, [%2];"
                 : "=r"(r[0]), "=r"(r[1]) : "r"(addr));
}
__device__ __forceinline__ void mma_bf16(float c[4], const uint32_t a[4],
                                         uint32_t b0, uint32_t b1) {
    asm volatile(
        "mma.sync.aligned.m16n8k16.row.col.f32.bf16.bf16.f32 "
        "{%0,%1,%2,%3}, {%4,%5,%6,%7}, {%8,%9}, {%0,%1,%2,%3};"
        : "+f"(c[0]), "+f"(c[1]), "+f"(c[2]), "+f"(c[3])
        : "r"(a[0]), "r"(a[1]), "r"(a[2]), "r"(a[3]), "r"(b0), "r"(b1));
}
__device__ __forceinline__ void cp16(uint32_t dst, const void* src) {
    asm volatile("cp.async.cg.shared.global [%0], [%1], 16;" :: "r"(dst), "l"(src) : "memory");
}

// ---------------- prep: z, gelu derivatives ----------------
__global__ void prep_kernel(const float* __restrict__ x,
                            const float* __restrict__ W1,
                            const float* __restrict__ b1) {
    int b = blockIdx.x;
    __shared__ float xs[D];
    int t = threadIdx.x;
    if (t < D) xs[t] = x[b * D + t];
    __syncthreads();
    if (t < D) {
        const float* w = W1 + t * D;
        float z = b1[t];
        #pragma unroll 4
        for (int i = 0; i < D; i++) z = fmaf(w[i], xs[i], z);
        float cdf = 0.5f * (1.0f + erff(z * 0.70710678118654752f));
        float pdf = 0.39894228040143268f * expf(-0.5f * z * z);
        g_G0[b * D + t] = z * cdf;
        g_G1[b * D + t] = cdf + z * pdf;
        g_G2[b * D + t] = (2.0f - z * z) * pdf;
    }
}

__global__ void out_kernel(const float* __restrict__ W2,
                           const float* __restrict__ b2,
                           float* __restrict__ out) {
    int b = blockIdx.x;
    __shared__ float gs[D];
    int t = threadIdx.x;
    if (t < D) gs[t] = g_G0[b * D + t];
    __syncthreads();
    if (t < D) {
        const float* w = W2 + t * D;
        float acc = b2[t];
        #pragma unroll 4
        for (int k = 0; k < D; k++) acc = fmaf(w[k], gs[k], acc);
        out[b * D + t] = acc;
    }
}

// ---------------- A matrices: row-scaled W2 -> bf16 split ----------------
__global__ void buildA_kernel(const float* __restrict__ W2) {
    int m = blockIdx.x;          // m = b*100 + o
    int b = m / D, o = m % D;
    int k = threadIdx.x;         // 128
    float aj = 0.0f, ah = 0.0f;
    if (k < D) {
        float w = W2[o * D + k];
        aj = w * g_G1[b * D + k];
        ah = w * g_G2[b * D + k];
    }
    __nv_bfloat16 h, l;
    split_bf16(aj, h, l);
    g_AJh[m * KP + k] = h; g_AJl[m * KP + k] = l;
    split_bf16(ah, h, l);
    g_AHh[m * KP + k] = h; g_AHl[m * KP + k] = l;
}

// ---------------- Pt[n,k] = W1[k,i]*W1[k,j], bf16 split ----------------
__global__ void buildP_kernel(const float* __restrict__ W1) {
    int n = blockIdx.x;   // N_PAD
    int k = threadIdx.x;  // 128
    float v = 0.0f;
    if (n < D2 && k < D) {
        int i = n / D, j = n % D;
        v = __ldg(W1 + k * D + i) * __ldg(W1 + k * D + j);
    }
    __nv_bfloat16 h, l;
    split_bf16(v, h, l);
    g_PBh[(size_t)n * KP + k] = h;
    g_PBl[(size_t)n * KP + k] = l;
}

// ---------------- BJ[n=i,k] = W1[k,i], bf16 split ----------------
__global__ void buildBJ_kernel(const float* __restrict__ W1) {
    int n = blockIdx.x;   // 192
    int k = threadIdx.x;  // 128
    float v = (n < D && k < D) ? W1[k * D + n] : 0.0f;
    __nv_bfloat16 h, l;
    split_bf16(v, h, l);
    g_BJh[n * KP + k] = h;
    g_BJl[n * KP + k] = l;
}

// ---------------- HMMA GEMM ----------------
// C tile(128x96) = Ah*Bh + Ah*Bl + Al*Bh  (A:[m,KP], B:[n,KP], both K-major)
// which: 0 -> A=g_AJ*, B=g_BJ* ; 1 -> A=g_AH*, B=g_PB*
#define PITCH 240                          // bytes per smem row (112 bf16 + 8 pad); mult of 16
#define CHUNKS 14                          // 14*16B = 224B = 112 bf16 loaded per row
#define A_TILE_BYTES (128 * PITCH)         // 30720
#define B_TILE_BYTES (NTILE * PITCH)       // 23040
#define SMEM_BYTES (2 * A_TILE_BYTES + 2 * B_TILE_BYTES)  // 107520

template <int ROWS>
__device__ __forceinline__ void load_tile_async(uint32_t dst, const __nv_bfloat16* __restrict__ src,
                                                int row0, int tid) {
    constexpr int TOT = ROWS * CHUNKS;
    #pragma unroll
    for (int it = 0; it < (TOT + 255) / 256; it++) {
        int c = tid + it * 256;
        if (TOT % 256 != 0 && c >= TOT) break;
        int row = c / CHUNKS, col = c % CHUNKS;
        cp16(dst + row * PITCH + col * 16,
             src + (size_t)(row0 + row) * KP + col * 8);
    }
}

__global__ void __launch_bounds__(256, 2)
mma_gemm_kernel(float* __restrict__ C, int Nout, int which) {
    const __nv_bfloat16* __restrict__ Ah = which ? g_AHh : g_AJh;
    const __nv_bfloat16* __restrict__ Al = which ? g_AHl : g_AJl;
    const __nv_bfloat16* __restrict__ Bh = which ? g_PBh : g_BJh;
    const __nv_bfloat16* __restrict__ Bl = which ? g_PBl : g_BJl;

    extern __shared__ char smem[];
    uint32_t uAh = smem_to_u32(smem);
    uint32_t uAl = uAh + A_TILE_BYTES;
    uint32_t uBh = uAl + A_TILE_BYTES;
    uint32_t uBl = uBh + B_TILE_BYTES;

    int tid = threadIdx.x;
    int m0 = blockIdx.y * 128;
    int n0 = blockIdx.x * NTILE;

    load_tile_async<128>(uAh, Ah, m0, tid);
    load_tile_async<128>(uAl, Al, m0, tid);
    load_tile_async<NTILE>(uBh, Bh, n0, tid);
    load_tile_async<NTILE>(uBl, Bl, n0, tid);
    asm volatile("cp.async.commit_group;" ::: "memory");
    asm volatile("cp.async.wait_group 0;" ::: "memory");
    __syncthreads();

    int lane = tid & 31, wid = tid >> 5;
    int wm = (wid & 1) * 64;      // warp m-offset (2 m-warps)
    int wn = (wid >> 1) * 24;     // warp n-offset (4 n-warps x 24)
    int t = lane >> 3, r = lane & 7;

    // ldmatrix lane offsets (bytes)
    uint32_t aoff  = (uint32_t)((wm + (t & 1) * 8 + r) * PITCH + (t >> 1) * 16);
    uint32_t boff  = (uint32_t)((wn + (t >> 1) * 8 + r) * PITCH + (t & 1) * 16);
    uint32_t boff2 = (uint32_t)((wn + 16 + r) * PITCH + ((lane >> 3) & 1) * 16);

    float acc[4][3][4];
    #pragma unroll
    for (int i = 0; i < 4; i++)
        #pragma unroll
        for (int j = 0; j < 3; j++)
            #pragma unroll
            for (int e = 0; e < 4; e++) acc[i][j][e] = 0.0f;

    #pragma unroll
    for (int ks = 0; ks < K_STEPS; ks++) {
        uint32_t kb = ks * 32;
        uint32_t ah[4][4], al[4][4];
        uint32_t bh[6], bl[6];
        #pragma unroll
        for (int mf = 0; mf < 4; mf++) ldm4(ah[mf], uAh + aoff + mf * 16 * PITCH + kb);
        ldm4(bh, uBh + boff + kb);
        ldm2(bh + 4, uBh + boff2 + kb);
        #pragma unroll
        for (int mf = 0; mf < 4; mf++)
            #pragma unroll
            for (int nf = 0; nf < 3; nf++)
                mma_bf16(acc[mf][nf], ah[mf], bh[nf * 2], bh[nf * 2 + 1]);

        ldm4(bl, uBl + boff + kb);
        ldm2(bl + 4, uBl + boff2 + kb);
        #pragma unroll
        for (int mf = 0; mf < 4; mf++)
            #pragma unroll
            for (int nf = 0; nf < 3; nf++)
                mma_bf16(acc[mf][nf], ah[mf], bl[nf * 2], bl[nf * 2 + 1]);

        #pragma unroll
        for (int mf = 0; mf < 4; mf++) ldm4(al[mf], uAl + aoff + mf * 16 * PITCH + kb);
        #pragma unroll
        for (int mf = 0; mf < 4; mf++)
            #pragma unroll
            for (int nf = 0; nf < 3; nf++)
                mma_bf16(acc[mf][nf], al[mf], bh[nf * 2], bh[nf * 2 + 1]);
    }

    // epilogue: direct register -> gmem stores (float2; Nout even)
    #pragma unroll
    for (int mf = 0; mf < 4; mf++) {
        int m = m0 + wm + mf * 16 + (lane >> 2);
        #pragma unroll
        for (int nf = 0; nf < 3; nf++) {
            int n = n0 + wn + nf * 8 + 2 * (lane & 3);
            if (n < Nout) {
                float2 v0 = make_float2(acc[mf][nf][0], acc[mf][nf][1]);
                float2 v1 = make_float2(acc[mf][nf][2], acc[mf][nf][3]);
                *reinterpret_cast<float2*>(&C[(size_t)m * Nout + n]) = v0;
                *reinterpret_cast<float2*>(&C[(size_t)(m + 8) * Nout + n]) = v1;
            }
        }
    }
}

// ---------------- host ----------------
extern "C" void kernel_launch(void* const* d_in, const int* in_sizes, int n_in,
                              void* d_out, int out_size) {
    const float* x  = (const float*)d_in[0];
    const float* W1 = (const float*)d_in[1];
    const float* b1 = (const float*)d_in[2];
    const float* W2 = (const float*)d_in[3];
    const float* b2 = (const float*)d_in[4];

    float* out  = (float*)d_out;
    float* jac  = out + Bsz * D;
    float* hess = jac + (size_t)Bsz * D * D;

    cudaFuncSetAttribute(mma_gemm_kernel, cudaFuncAttributeMaxDynamicSharedMemorySize, SMEM_BYTES);

    prep_kernel<<<Bsz, 128>>>(x, W1, b1);
    out_kernel<<<Bsz, 128>>>(W2, b2, out);
    buildA_kernel<<<M_ROWS, 128>>>(W2);
    buildP_kernel<<<N_PAD, 128>>>(W1);
    buildBJ_kernel<<<NJ_PAD, 128>>>(W1);

    // jac = AJ(12800x100) @ W1^T-layout  (2 n-tiles)
    {
        dim3 grid(NJ_PAD / NTILE, M_ROWS / 128);
        mma_gemm_kernel<<<grid, 256, SMEM_BYTES>>>(jac, D, 0);
    }
    // hess = AH(12800x100) @ P(100x10000)  (105 n-tiles)
    {
        dim3 grid(N_PAD / NTILE, M_ROWS / 128);
        mma_gemm_kernel<<<grid, 256, SMEM_BYTES>>>(hess, D2, 1);
    }
}

// round 6
// speedup vs baseline: 4.2577x; 1.0751x over previous
#include <cuda_runtime.h>
#include <cuda_bf16.h>
#include <math.h>
#include <stdint.h>

#define Bsz 128
#define D 100
#define D2 10000
#define M_ROWS 12800      // B*D
#define KP 128            // padded K (storage in gmem scratch)
#define K_STEPS 7         // 7*16 = 112 >= 100
#define NTILE 64
#define NBLK 13           // i padded to 104 -> 13 blocks of 8
#define NPAIRS 91         // 13*14/2
#define N_SYM (NPAIRS * 64)   // 5824 packed hess columns
#define NJ_PAD 128        // 2 jac n-tiles

// ---------------- scratch (device globals) ----------------
__device__ float g_G0[M_ROWS];
__device__ float g_G1[M_ROWS];
__device__ float g_G2[M_ROWS];
__device__ __nv_bfloat16 g_AJh[M_ROWS * KP];
__device__ __nv_bfloat16 g_AJl[M_ROWS * KP];
__device__ __nv_bfloat16 g_AHh[M_ROWS * KP];
__device__ __nv_bfloat16 g_AHl[M_ROWS * KP];
__device__ __nv_bfloat16 g_PBh[(size_t)N_SYM * KP];   // packed sym P
__device__ __nv_bfloat16 g_PBl[(size_t)N_SYM * KP];
__device__ __nv_bfloat16 g_BJh[NJ_PAD * KP];          // BJ[n=i,k] = W1[k,i]
__device__ __nv_bfloat16 g_BJl[NJ_PAD * KP];

// ---------------- helpers ----------------
__device__ __forceinline__ uint32_t smem_to_u32(const void* p) {
    uint32_t a;
    asm("{ .reg .u64 t; cvta.to.shared.u64 t, %1; cvt.u32.u64 %0, t; }" : "=r"(a) : "l"(p));
    return a;
}
__device__ __forceinline__ void split_bf16(float v, __nv_bfloat16& h, __nv_bfloat16& l) {
    h = __float2bfloat16_rn(v);
    l = __float2bfloat16_rn(v - __bfloat162float(h));
}
__device__ __forceinline__ void ldm4(uint32_t r[4], uint32_t addr) {
    asm volatile("ldmatrix.sync.aligned.m8n8.x4.shared.b16 {%0,%1,%2,%3}, [%4];"
                 : "=r"(r[0]), "=r"(r[1]), "=r"(r[2]), "=r"(r[3]) : "r"(addr));
}
__device__ __forceinline__ void mma_bf16(float c[4], const uint32_t a[4],
                                         uint32_t b0, uint32_t b1) {
    asm volatile(
        "mma.sync.aligned.m16n8k16.row.col.f32.bf16.bf16.f32 "
        "{%0,%1,%2,%3}, {%4,%5,%6,%7}, {%8,%9}, {%0,%1,%2,%3};"
        : "+f"(c[0]), "+f"(c[1]), "+f"(c[2]), "+f"(c[3])
        : "r"(a[0]), "r"(a[1]), "r"(a[2]), "r"(a[3]), "r"(b0), "r"(b1));
}
__device__ __forceinline__ void cp16(uint32_t dst, const void* src) {
    asm volatile("cp.async.cg.shared.global [%0], [%1], 16;" :: "r"(dst), "l"(src) : "memory");
}
__device__ __forceinline__ void decode_pair(int t, int& bi, int& bj) {
    int b = 0, rem = t;
    while (rem >= NBLK - b) { rem -= NBLK - b; b++; }
    bi = b; bj = b + rem;
}

// ---------------- prep: z, gelu derivatives ----------------
__global__ void prep_kernel(const float* __restrict__ x,
                            const float* __restrict__ W1,
                            const float* __restrict__ b1) {
    int b = blockIdx.x;
    __shared__ float xs[D];
    int t = threadIdx.x;
    if (t < D) xs[t] = x[b * D + t];
    __syncthreads();
    if (t < D) {
        const float* w = W1 + t * D;
        float z = b1[t];
        #pragma unroll 4
        for (int i = 0; i < D; i++) z = fmaf(w[i], xs[i], z);
        float cdf = 0.5f * (1.0f + erff(z * 0.70710678118654752f));
        float pdf = 0.39894228040143268f * expf(-0.5f * z * z);
        g_G0[b * D + t] = z * cdf;
        g_G1[b * D + t] = cdf + z * pdf;
        g_G2[b * D + t] = (2.0f - z * z) * pdf;
    }
}

__global__ void out_kernel(const float* __restrict__ W2,
                           const float* __restrict__ b2,
                           float* __restrict__ out) {
    int b = blockIdx.x;
    __shared__ float gs[D];
    int t = threadIdx.x;
    if (t < D) gs[t] = g_G0[b * D + t];
    __syncthreads();
    if (t < D) {
        const float* w = W2 + t * D;
        float acc = b2[t];
        #pragma unroll 4
        for (int k = 0; k < D; k++) acc = fmaf(w[k], gs[k], acc);
        out[b * D + t] = acc;
    }
}

// ---------------- A matrices: row-scaled W2 -> bf16 split ----------------
__global__ void buildA_kernel(const float* __restrict__ W2) {
    int m = blockIdx.x;          // m = b*100 + o
    int b = m / D, o = m % D;
    int k = threadIdx.x;         // 128
    float aj = 0.0f, ah = 0.0f;
    if (k < D) {
        float w = W2[o * D + k];
        aj = w * g_G1[b * D + k];
        ah = w * g_G2[b * D + k];
    }
    __nv_bfloat16 h, l;
    split_bf16(aj, h, l);
    g_AJh[m * KP + k] = h; g_AJl[m * KP + k] = l;
    split_bf16(ah, h, l);
    g_AHh[m * KP + k] = h; g_AHl[m * KP + k] = l;
}

// ---------------- packed symmetric P columns ----------------
__global__ void buildP_kernel(const float* __restrict__ W1) {
    int n = blockIdx.x;   // 0..N_SYM-1
    int k = threadIdx.x;  // 128
    int t = n >> 6, nl = n & 63;
    int bi, bj; decode_pair(t, bi, bj);
    int i = bi * 8 + (nl >> 3);
    int j = bj * 8 + (nl & 7);
    float v = 0.0f;
    if (i < D && j < D && k < D)
        v = __ldg(W1 + k * D + i) * __ldg(W1 + k * D + j);
    __nv_bfloat16 h, l;
    split_bf16(v, h, l);
    g_PBh[(size_t)n * KP + k] = h;
    g_PBl[(size_t)n * KP + k] = l;
}

// ---------------- BJ[n=i,k] = W1[k,i], bf16 split ----------------
__global__ void buildBJ_kernel(const float* __restrict__ W1) {
    int n = blockIdx.x;   // 128
    int k = threadIdx.x;  // 128
    float v = (n < D && k < D) ? W1[k * D + n] : 0.0f;
    __nv_bfloat16 h, l;
    split_bf16(v, h, l);
    g_BJh[n * KP + k] = h;
    g_BJl[n * KP + k] = l;
}

// ---------------- HMMA GEMM, 128x64 tile, 3-term bf16 split ----------------
// mode 0: jac (plain write, n0 = bx*64, Nout=100)
// mode 1: hess symmetric (bx = pair tile; write (i,j) and (j,i))
#define PITCH 240                          // bytes per smem row (112 bf16 + pad)
#define CHUNKS 14
#define A_TILE_BYTES (128 * PITCH)         // 30720
#define B_TILE_BYTES (NTILE * PITCH)       // 15360
#define SMEM_BYTES (2 * A_TILE_BYTES + 2 * B_TILE_BYTES)  // 92160
#define CPITCH 66                          // C staging pitch (floats)

template <int ROWS>
__device__ __forceinline__ void load_tile_async(uint32_t dst, const __nv_bfloat16* __restrict__ src,
                                                int row0, int tid) {
    constexpr int TOT = ROWS * CHUNKS;
    #pragma unroll
    for (int it = 0; it < (TOT + 255) / 256; it++) {
        int c = tid + it * 256;
        if (TOT % 256 != 0 && c >= TOT) break;
        int row = c / CHUNKS, col = c % CHUNKS;
        cp16(dst + row * PITCH + col * 16,
             src + (size_t)(row0 + row) * KP + col * 8);
    }
}

__global__ void __launch_bounds__(256, 2)
mma_gemm_kernel(float* __restrict__ C, int mode) {
    const __nv_bfloat16* __restrict__ Ah = mode ? g_AHh : g_AJh;
    const __nv_bfloat16* __restrict__ Al = mode ? g_AHl : g_AJl;
    const __nv_bfloat16* __restrict__ Bh = mode ? g_PBh : g_BJh;
    const __nv_bfloat16* __restrict__ Bl = mode ? g_PBl : g_BJl;

    extern __shared__ char smem[];
    uint32_t uAh = smem_to_u32(smem);
    uint32_t uAl = uAh + A_TILE_BYTES;
    uint32_t uBh = uAl + A_TILE_BYTES;
    uint32_t uBl = uBh + B_TILE_BYTES;

    int tid = threadIdx.x;
    int m0 = blockIdx.y * 128;
    int n0 = blockIdx.x * NTILE;

    load_tile_async<128>(uAh, Ah, m0, tid);
    load_tile_async<128>(uAl, Al, m0, tid);
    load_tile_async<NTILE>(uBh, Bh, n0, tid);
    load_tile_async<NTILE>(uBl, Bl, n0, tid);
    asm volatile("cp.async.commit_group;" ::: "memory");
    asm volatile("cp.async.wait_group 0;" ::: "memory");
    __syncthreads();

    int lane = tid & 31, wid = tid >> 5;
    int wm = (wid & 1) * 64;      // 2 m-warps
    int wn = (wid >> 1) * 16;     // 4 n-warps x 16
    int t = lane >> 3, r = lane & 7;

    uint32_t aoff = (uint32_t)((wm + (t & 1) * 8 + r) * PITCH + (t >> 1) * 16);
    uint32_t boff = (uint32_t)((wn + (t >> 1) * 8 + r) * PITCH + (t & 1) * 16);

    float acc[4][2][4];
    #pragma unroll
    for (int i = 0; i < 4; i++)
        #pragma unroll
        for (int j = 0; j < 2; j++)
            #pragma unroll
            for (int e = 0; e < 4; e++) acc[i][j][e] = 0.0f;

    #pragma unroll
    for (int ks = 0; ks < K_STEPS; ks++) {
        uint32_t kb = ks * 32;
        uint32_t ah[4][4], al[4][4], bh[4], bl[4];
        #pragma unroll
        for (int mf = 0; mf < 4; mf++) ldm4(ah[mf], uAh + aoff + mf * 16 * PITCH + kb);
        ldm4(bh, uBh + boff + kb);
        #pragma unroll
        for (int mf = 0; mf < 4; mf++)
            #pragma unroll
            for (int nf = 0; nf < 2; nf++)
                mma_bf16(acc[mf][nf], ah[mf], bh[nf * 2], bh[nf * 2 + 1]);

        ldm4(bl, uBl + boff + kb);
        #pragma unroll
        for (int mf = 0; mf < 4; mf++)
            #pragma unroll
            for (int nf = 0; nf < 2; nf++)
                mma_bf16(acc[mf][nf], ah[mf], bl[nf * 2], bl[nf * 2 + 1]);

        #pragma unroll
        for (int mf = 0; mf < 4; mf++) ldm4(al[mf], uAl + aoff + mf * 16 * PITCH + kb);
        #pragma unroll
        for (int mf = 0; mf < 4; mf++)
            #pragma unroll
            for (int nf = 0; nf < 2; nf++)
                mma_bf16(acc[mf][nf], al[mf], bh[nf * 2], bh[nf * 2 + 1]);
    }

    // ---- stage C tile in smem (reuse A region) ----
    __syncthreads();
    float* Cs = reinterpret_cast<float*>(smem);
    #pragma unroll
    for (int mf = 0; mf < 4; mf++) {
        int mrow = wm + mf * 16 + (lane >> 2);
        #pragma unroll
        for (int nf = 0; nf < 2; nf++) {
            int ncol = wn + nf * 8 + 2 * (lane & 3);
            Cs[mrow * CPITCH + ncol]       = acc[mf][nf][0];
            Cs[mrow * CPITCH + ncol + 1]   = acc[mf][nf][1];
            Cs[(mrow + 8) * CPITCH + ncol]     = acc[mf][nf][2];
            Cs[(mrow + 8) * CPITCH + ncol + 1] = acc[mf][nf][3];
        }
    }
    __syncthreads();

    if (mode == 0) {
        // jac: plain write, cols n0..n0+63, guard < 100
        #pragma unroll
        for (int it = 0; it < 32; it++) {
            int e = tid + it * 256;
            int m = e >> 6, nl = e & 63;
            int n = n0 + nl;
            if (n < D) C[(size_t)(m0 + m) * D + n] = Cs[m * CPITCH + nl];
        }
    } else {
        int bi, bj; decode_pair(blockIdx.x, bi, bj);
        // phase 1: primary (i,j)
        #pragma unroll
        for (int it = 0; it < 32; it++) {
            int e = tid + it * 256;
            int m = e >> 6, nl = e & 63;
            int i = bi * 8 + (nl >> 3), j = bj * 8 + (nl & 7);
            if (i < D && j < D)
                C[(size_t)(m0 + m) * D2 + i * D + j] = Cs[m * CPITCH + nl];
        }
        // phase 2: mirror (j,i) — consecutive tid -> consecutive i (coalesced)
        #pragma unroll
        for (int it = 0; it < 32; it++) {
            int e = tid + it * 256;
            int m = e >> 6, nl = e & 63;
            int lj = nl >> 3, li = nl & 7;
            int i = bi * 8 + li, j = bj * 8 + lj;
            if (i < D && j < D)
                C[(size_t)(m0 + m) * D2 + j * D + i] = Cs[m * CPITCH + li * 8 + lj];
        }
    }
}

// ---------------- host ----------------
extern "C" void kernel_launch(void* const* d_in, const int* in_sizes, int n_in,
                              void* d_out, int out_size) {
    const float* x  = (const float*)d_in[0];
    const float* W1 = (const float*)d_in[1];
    const float* b1 = (const float*)d_in[2];
    const float* W2 = (const float*)d_in[3];
    const float* b2 = (const float*)d_in[4];

    float* out  = (float*)d_out;
    float* jac  = out + Bsz * D;
    float* hess = jac + (size_t)Bsz * D * D;

    cudaFuncSetAttribute(mma_gemm_kernel, cudaFuncAttributeMaxDynamicSharedMemorySize, SMEM_BYTES);

    prep_kernel<<<Bsz, 128>>>(x, W1, b1);
    out_kernel<<<Bsz, 128>>>(W2, b2, out);
    buildA_kernel<<<M_ROWS, 128>>>(W2);
    buildP_kernel<<<N_SYM, 128>>>(W1);
    buildBJ_kernel<<<NJ_PAD, 128>>>(W1);

    // jac = AJ(12800x100) @ W1^T-layout  (2 n-tiles of 64)
    {
        dim3 grid(NJ_PAD / NTILE, M_ROWS / 128);
        mma_gemm_kernel<<<grid, 256, SMEM_BYTES>>>(jac, 0);
    }
    // hess: 91 symmetric pair-tiles x 100 m-tiles
    {
        dim3 grid(NPAIRS, M_ROWS / 128);
        mma_gemm_kernel<<<grid, 256, SMEM_BYTES>>>(hess, 1);
    }
}